// round 7
// baseline (speedup 1.0000x reference)
#include <cuda_runtime.h>
#include <cuda_bf16.h>
#include <cstdint>

// Problem dims (fixed)
#define B_   8
#define L_   2048
#define E_   1024
#define M_   (B_ * L_)   // 16384
#define RAD  8

// ---------------------------------------------------------------------------
// Scratch (__device__ globals; allocation-free rule)
// ---------------------------------------------------------------------------
__device__ __nv_bfloat16 g_Xh[(size_t)M_ * E_];
__device__ __nv_bfloat16 g_Xl[(size_t)M_ * E_];
__device__ __nv_bfloat16 g_Wih[(size_t)E_ * E_];
__device__ __nv_bfloat16 g_Wil[(size_t)E_ * E_];
__device__ __nv_bfloat16 g_Woh[(size_t)E_ * E_];
__device__ __nv_bfloat16 g_Wol[(size_t)E_ * E_];
__device__ float         g_Vf [(size_t)M_ * E_];
__device__ __nv_bfloat16 g_Uh[(size_t)M_ * E_];
__device__ __nv_bfloat16 g_Ul[(size_t)M_ * E_];

__device__ __forceinline__ uint32_t smem_u32(const void* p) {
    uint32_t a;
    asm("{ .reg .u64 t; cvta.to.shared.u64 t, %1; cvt.u32.u64 %0, t; }" : "=r"(a) : "l"(p));
    return a;
}

#define CP_ASYNC16(dst, src) \
    asm volatile("cp.async.cg.shared.global [%0], [%1], 16;" :: "r"(dst), "l"(src))
#define CP_COMMIT() asm volatile("cp.async.commit_group;")
#define CP_WAIT(n)  asm volatile("cp.async.wait_group %0;" :: "n"(n))

// ---------------------------------------------------------------------------
// GEMM: C[M,1024] = A[M,1024] @ W[1024,1024]^T via bf16 split (3 HMMA terms).
// BM=256, BN=128, BK=32, 512 threads (16 warps, warp tile 32x64),
// 3-stage cp.async pipeline. smem rows = 64B (4 x 16B segs) with swizzle
// seg16 ^ (((row>>1)&3)<<4) -> conflict-free ldmatrix.
// Stage = Ah(16K)+Al(16K)+Wh(8K)+Wl(8K) = 48KB; 3 stages = 144KB, 1 CTA/SM.
// Per-thread fill: 6 x cp.async 16B (2 Ah, 2 Al, 1 Wh, 1 Wl) = 3072 ops total.
// ---------------------------------------------------------------------------
#define GBM 256
#define GBN 128
#define GBK 32
#define NCHUNK (E_ / GBK)   // 32

#define T_AH 0
#define T_AL 16384
#define T_WH 32768
#define T_WL 40960
#define STG_BYTES 49152
#define SM_TOTAL (3 * STG_BYTES)   // 147456

__global__ __launch_bounds__(512, 1) void gemm_mma(
    const __nv_bfloat16* __restrict__ Ah, const __nv_bfloat16* __restrict__ Al,
    const __nv_bfloat16* __restrict__ Wh, const __nv_bfloat16* __restrict__ Wl,
    float* __restrict__ C)
{
    extern __shared__ char smem[];
    const uint32_t smem_base = smem_u32(smem);

    const int tid  = threadIdx.x;
    const int wid  = tid >> 5;
    const int lane = tid & 31;
    const int wm   = wid & 7;    // M offset wm*32
    const int wn   = wid >> 3;   // N offset wn*64

    const size_t mrow0 = (size_t)blockIdx.y * GBM;
    const size_t nrow0 = (size_t)blockIdx.x * GBN;

    // --- cp.async per-thread addressing ---
    // A tiles: 256 rows x 4 segs = 1024 chunks -> 2 reps of 512 threads.
    // W tiles: 128 rows x 4 segs = 512 chunks -> 1 rep.
    const int rA0 = tid >> 2;              // 0..127
    const int rA1 = rA0 + 128;             // 128..255
    const int sg  = tid & 3;               // 16B segment 0..3
    const uint32_t soA0 = (uint32_t)rA0 * 64 + (uint32_t)((sg * 16) ^ (((rA0 >> 1) & 3) << 4));
    const uint32_t soA1 = (uint32_t)rA1 * 64 + (uint32_t)((sg * 16) ^ (((rA1 >> 1) & 3) << 4));
    const uint32_t soW  = soA0;            // W rows 0..127, same pattern
    const __nv_bfloat16* gAh0 = Ah + (mrow0 + rA0) * E_ + sg * 8;
    const __nv_bfloat16* gAh1 = Ah + (mrow0 + rA1) * E_ + sg * 8;
    const __nv_bfloat16* gAl0 = Al + (mrow0 + rA0) * E_ + sg * 8;
    const __nv_bfloat16* gAl1 = Al + (mrow0 + rA1) * E_ + sg * 8;
    const __nv_bfloat16* gWh  = Wh + (nrow0 + rA0) * E_ + sg * 8;
    const __nv_bfloat16* gWl  = Wl + (nrow0 + rA0) * E_ + sg * 8;

    // --- ldmatrix lane addressing (64B rows) ---
    uint32_t aBase[2], aSwz[2];
#pragma unroll
    for (int mt = 0; mt < 2; mt++) {
        const int r = wm * 32 + mt * 16 + (lane & 15);
        aBase[mt] = (uint32_t)r * 64;
        aSwz[mt]  = (uint32_t)(((r >> 1) & 3) << 4);
    }
    const uint32_t cselA = (uint32_t)(((lane >> 4) & 1) * 16);
    uint32_t bBase[4], bSwz[4];
#pragma unroll
    for (int g = 0; g < 4; g++) {
        const int r = wn * 64 + g * 16 + (lane & 7) + ((lane >> 4) & 1) * 8;
        bBase[g] = (uint32_t)r * 64;
        bSwz[g]  = (uint32_t)(((r >> 1) & 3) << 4);
    }
    const uint32_t cselB = (uint32_t)(((lane >> 3) & 1) * 16);

    float acc[2][8][4];
#pragma unroll
    for (int mt = 0; mt < 2; mt++)
#pragma unroll
        for (int nt = 0; nt < 8; nt++)
#pragma unroll
            for (int r = 0; r < 4; r++) acc[mt][nt][r] = 0.0f;

    auto load_chunk = [&](int ch, int stg) {
        const uint32_t sb = smem_base + (uint32_t)stg * STG_BYTES;
        const int kb = ch * GBK;
        CP_ASYNC16(sb + T_AH + soA0, gAh0 + kb);
        CP_ASYNC16(sb + T_AH + soA1, gAh1 + kb);
        CP_ASYNC16(sb + T_AL + soA0, gAl0 + kb);
        CP_ASYNC16(sb + T_AL + soA1, gAl1 + kb);
        CP_ASYNC16(sb + T_WH + soW,  gWh  + kb);
        CP_ASYNC16(sb + T_WL + soW,  gWl  + kb);
        CP_COMMIT();
    };

    load_chunk(0, 0);
    load_chunk(1, 1);

#pragma unroll 1
    for (int ch = 0; ch < NCHUNK; ch++) {
        if (ch + 1 < NCHUNK) { CP_WAIT(1); } else { CP_WAIT(0); }
        __syncthreads();
        if (ch + 2 < NCHUNK) load_chunk(ch + 2, (ch + 2) % 3);

        const uint32_t sb = smem_base + (uint32_t)(ch % 3) * STG_BYTES;
#pragma unroll
        for (int term = 0; term < 3; term++) {
            const uint32_t baseA = sb + (term == 2 ? T_AL : T_AH);
            const uint32_t baseW = sb + (term == 1 ? T_WL : T_WH);
#pragma unroll
            for (int ks = 0; ks < 2; ks++) {
                const uint32_t kb = (uint32_t)(ks * 32);
                uint32_t a[2][4];
#pragma unroll
                for (int mt = 0; mt < 2; mt++) {
                    const uint32_t ad = baseA + aBase[mt] + ((kb + cselA) ^ aSwz[mt]);
                    asm volatile(
                        "ldmatrix.sync.aligned.m8n8.x4.shared.b16 {%0,%1,%2,%3}, [%4];"
                        : "=r"(a[mt][0]), "=r"(a[mt][1]), "=r"(a[mt][2]), "=r"(a[mt][3])
                        : "r"(ad));
                }
#pragma unroll
                for (int g = 0; g < 4; g++) {
                    uint32_t b0, b1, b2, b3;
                    const uint32_t bd = baseW + bBase[g] + ((kb + cselB) ^ bSwz[g]);
                    asm volatile(
                        "ldmatrix.sync.aligned.m8n8.x4.shared.b16 {%0,%1,%2,%3}, [%4];"
                        : "=r"(b0), "=r"(b1), "=r"(b2), "=r"(b3)
                        : "r"(bd));
#pragma unroll
                    for (int mt = 0; mt < 2; mt++) {
                        asm volatile(
                            "mma.sync.aligned.m16n8k16.row.col.f32.bf16.bf16.f32 "
                            "{%0,%1,%2,%3}, {%4,%5,%6,%7}, {%8,%9}, {%0,%1,%2,%3};"
                            : "+f"(acc[mt][g * 2][0]), "+f"(acc[mt][g * 2][1]),
                              "+f"(acc[mt][g * 2][2]), "+f"(acc[mt][g * 2][3])
                            : "r"(a[mt][0]), "r"(a[mt][1]), "r"(a[mt][2]), "r"(a[mt][3]),
                              "r"(b0), "r"(b1));
                        asm volatile(
                            "mma.sync.aligned.m16n8k16.row.col.f32.bf16.bf16.f32 "
                            "{%0,%1,%2,%3}, {%4,%5,%6,%7}, {%8,%9}, {%0,%1,%2,%3};"
                            : "+f"(acc[mt][g * 2 + 1][0]), "+f"(acc[mt][g * 2 + 1][1]),
                              "+f"(acc[mt][g * 2 + 1][2]), "+f"(acc[mt][g * 2 + 1][3])
                            : "r"(a[mt][0]), "r"(a[mt][1]), "r"(a[mt][2]), "r"(a[mt][3]),
                              "r"(b2), "r"(b3));
                    }
                }
            }
        }
    }

    // Epilogue: warp tile rows wm*32+mt*16+{qr,qr+8}, cols wn*64+nt*8+qc.
    const int qr = lane >> 2;
    const int qc = (lane & 3) * 2;
#pragma unroll
    for (int mt = 0; mt < 2; mt++) {
        const size_t r0 = mrow0 + wm * 32 + mt * 16 + qr;
#pragma unroll
        for (int nt = 0; nt < 8; nt++) {
            const size_t col = nrow0 + wn * 64 + nt * 8 + qc;
            *(float2*)(C + r0 * E_ + col)       = make_float2(acc[mt][nt][0], acc[mt][nt][1]);
            *(float2*)(C + (r0 + 8) * E_ + col) = make_float2(acc[mt][nt][2], acc[mt][nt][3]);
        }
    }
}

// ---------------------------------------------------------------------------
// fp32 -> bf16 hi/lo split conversion (float4 vectorized)
// ---------------------------------------------------------------------------
__global__ __launch_bounds__(256) void conv_split(
    const float* __restrict__ in, __nv_bfloat16* __restrict__ hi,
    __nv_bfloat16* __restrict__ lo, int n4)
{
    int idx = blockIdx.x * 256 + threadIdx.x;
    if (idx >= n4) return;
    float4 v = ((const float4*)in)[idx];
    __nv_bfloat16 h0 = __float2bfloat16(v.x), h1 = __float2bfloat16(v.y);
    __nv_bfloat16 h2 = __float2bfloat16(v.z), h3 = __float2bfloat16(v.w);
    __nv_bfloat16 l0 = __float2bfloat16(v.x - __bfloat162float(h0));
    __nv_bfloat16 l1 = __float2bfloat16(v.y - __bfloat162float(h1));
    __nv_bfloat16 l2 = __float2bfloat16(v.z - __bfloat162float(h2));
    __nv_bfloat16 l3 = __float2bfloat16(v.w - __bfloat162float(h3));
    __nv_bfloat162 hp0; hp0.x = h0; hp0.y = h1;
    __nv_bfloat162 hp1; hp1.x = h2; hp1.y = h3;
    __nv_bfloat162 lp0; lp0.x = l0; lp0.y = l1;
    __nv_bfloat162 lp1; lp1.x = l2; lp1.y = l3;
    uint2 hw, lw;
    hw.x = *(uint32_t*)&hp0; hw.y = *(uint32_t*)&hp1;
    lw.x = *(uint32_t*)&lp0; lw.y = *(uint32_t*)&lp1;
    ((uint2*)hi)[idx] = hw;
    ((uint2*)lo)[idx] = lw;
}

// ---------------------------------------------------------------------------
// Gaussian smoothing along sequence (17 taps, float4 over embed dim),
// reading fp32 V, writing bf16 hi/lo U for GEMM2.
// ---------------------------------------------------------------------------
__global__ __launch_bounds__(256) void smooth_kernel(
    const float* __restrict__ V, __nv_bfloat16* __restrict__ Uh,
    __nv_bfloat16* __restrict__ Ul)
{
    const float wt[RAD + 1] = {1.0f, 0.60653066f, 0.13533528f, 0.011108997f,
                               3.3546263e-4f, 3.7266532e-6f, 1.5229979e-8f,
                               2.2897348e-11f, 1.2664166e-14f};
    const int n = blockIdx.x;        // b*L + q
    const int b = n >> 11;
    const int q = n & (L_ - 1);
    const int e = threadIdx.x * 4;   // 4 consecutive embed cols
    const int h = e >> 7;            // head

    int c;
    switch (h) {
        case 0: case 5: c = q;      break;   // center
        case 1: case 6: c = q - 1;  break;   // left
        case 2: case 7: c = q + 1;  break;   // right
        case 3:         c = 0;      break;   // first
        default:        c = L_ - 1; break;   // last
    }

    float ax = 0.f, ay = 0.f, az = 0.f, aw = 0.f, wsum = 0.f;
#pragma unroll
    for (int d = -RAD; d <= RAD; d++) {
        const int j = c + d;
        if (j >= 0 && j < L_) {
            const float w = wt[d < 0 ? -d : d];
            wsum += w;
            const float4 v = *(const float4*)(V + ((size_t)b * L_ + j) * E_ + e);
            ax = fmaf(w, v.x, ax); ay = fmaf(w, v.y, ay);
            az = fmaf(w, v.z, az); aw = fmaf(w, v.w, aw);
        }
    }
    const float inv = 1.0f / wsum;
    ax *= inv; ay *= inv; az *= inv; aw *= inv;

    __nv_bfloat16 h0 = __float2bfloat16(ax), h1 = __float2bfloat16(ay);
    __nv_bfloat16 h2 = __float2bfloat16(az), h3 = __float2bfloat16(aw);
    __nv_bfloat16 l0 = __float2bfloat16(ax - __bfloat162float(h0));
    __nv_bfloat16 l1 = __float2bfloat16(ay - __bfloat162float(h1));
    __nv_bfloat16 l2 = __float2bfloat16(az - __bfloat162float(h2));
    __nv_bfloat16 l3 = __float2bfloat16(aw - __bfloat162float(h3));
    __nv_bfloat162 hp0; hp0.x = h0; hp0.y = h1;
    __nv_bfloat162 hp1; hp1.x = h2; hp1.y = h3;
    __nv_bfloat162 lp0; lp0.x = l0; lp0.y = l1;
    __nv_bfloat162 lp1; lp1.x = l2; lp1.y = l3;
    uint2 hw, lw;
    hw.x = *(uint32_t*)&hp0; hw.y = *(uint32_t*)&hp1;
    lw.x = *(uint32_t*)&lp0; lw.y = *(uint32_t*)&lp1;
    const size_t o = ((size_t)n * E_ + e) >> 2;
    ((uint2*)Uh)[o] = hw;
    ((uint2*)Ul)[o] = lw;
}

// ---------------------------------------------------------------------------
extern "C" void kernel_launch(void* const* d_in, const int* in_sizes, int n_in,
                              void* d_out, int out_size)
{
    (void)in_sizes; (void)n_in; (void)out_size;
    const float* x     = (const float*)d_in[0];
    const float* W_in  = (const float*)d_in[1];
    const float* W_out = (const float*)d_in[2];
    float* out = (float*)d_out;

    __nv_bfloat16 *Xh, *Xl, *Wih, *Wil, *Woh, *Wol, *Uh, *Ul;
    float* Vf;
    cudaGetSymbolAddress((void**)&Xh, g_Xh);
    cudaGetSymbolAddress((void**)&Xl, g_Xl);
    cudaGetSymbolAddress((void**)&Wih, g_Wih);
    cudaGetSymbolAddress((void**)&Wil, g_Wil);
    cudaGetSymbolAddress((void**)&Woh, g_Woh);
    cudaGetSymbolAddress((void**)&Wol, g_Wol);
    cudaGetSymbolAddress((void**)&Vf, g_Vf);
    cudaGetSymbolAddress((void**)&Uh, g_Uh);
    cudaGetSymbolAddress((void**)&Ul, g_Ul);

    cudaFuncSetAttribute(gemm_mma, cudaFuncAttributeMaxDynamicSharedMemorySize, SM_TOTAL);

    // Split conversions
    conv_split<<<(M_ * E_ / 4 + 255) / 256, 256>>>(x, Xh, Xl, M_ * E_ / 4);
    conv_split<<<(E_ * E_ / 4 + 255) / 256, 256>>>(W_in, Wih, Wil, E_ * E_ / 4);
    conv_split<<<(E_ * E_ / 4 + 255) / 256, 256>>>(W_out, Woh, Wol, E_ * E_ / 4);

    dim3 gridGemm(E_ / GBN, M_ / GBM);   // (8, 64)
    // V = X @ W_in^T   (fp32 out for smoothing)
    gemm_mma<<<gridGemm, 512, SM_TOTAL>>>(Xh, Xl, Wih, Wil, Vf);
    // U = gaussian smooth of V (bf16 hi/lo out)
    smooth_kernel<<<M_, 256>>>(Vf, Uh, Ul);
    // out = U @ W_out^T (fp32 out)
    gemm_mma<<<gridGemm, 512, SM_TOTAL>>>(Uh, Ul, Woh, Wol, out);
}

// round 8
// speedup vs baseline: 1.2514x; 1.2514x over previous
#include <cuda_runtime.h>
#include <cuda_bf16.h>
#include <cstdint>

// Problem dims (fixed)
#define B_   8
#define L_   2048
#define E_   1024
#define M_   (B_ * L_)   // 16384
#define RAD  8

// ---------------------------------------------------------------------------
// Scratch (__device__ globals; allocation-free rule)
// ---------------------------------------------------------------------------
__device__ __nv_bfloat16 g_Xh[(size_t)M_ * E_];
__device__ __nv_bfloat16 g_Xl[(size_t)M_ * E_];
__device__ __nv_bfloat16 g_Wih[(size_t)E_ * E_];
__device__ __nv_bfloat16 g_Wil[(size_t)E_ * E_];
__device__ __nv_bfloat16 g_Woh[(size_t)E_ * E_];
__device__ __nv_bfloat16 g_Wol[(size_t)E_ * E_];
__device__ float         g_Vf [(size_t)M_ * E_];
__device__ __nv_bfloat16 g_Uh[(size_t)M_ * E_];
__device__ __nv_bfloat16 g_Ul[(size_t)M_ * E_];

__device__ __forceinline__ uint32_t smem_u32(const void* p) {
    uint32_t a;
    asm("{ .reg .u64 t; cvta.to.shared.u64 t, %1; cvt.u32.u64 %0, t; }" : "=r"(a) : "l"(p));
    return a;
}

#define CP_ASYNC16(dst, src) \
    asm volatile("cp.async.cg.shared.global [%0], [%1], 16;" :: "r"(dst), "l"(src))
#define CP_COMMIT() asm volatile("cp.async.commit_group;")
#define CP_WAIT(n)  asm volatile("cp.async.wait_group %0;" :: "n"(n))

// ---------------------------------------------------------------------------
// GEMM: C[M,1024] = A[M,1024] @ W[1024,1024]^T via bf16 split (3 HMMA terms).
// BM=BN=128, BK=32, 256 threads (8 warps, warp tile 32x64), 3-stage cp.async.
// smem rows = 64B (4 x 16B segs), swizzle seg16 ^ (((row>>1)&3)<<4).
// Stage = 4 tiles x 8KB = 32KB; 3 stages = 96KB -> 2 CTAs/SM (the two CTAs
// are barrier-independent, covering each other's chunk-boundary bubbles).
// ---------------------------------------------------------------------------
#define GBM 128
#define GBN 128
#define GBK 32
#define NCHUNK (E_ / GBK)   // 32

#define T_AH 0
#define T_AL 8192
#define T_WH 16384
#define T_WL 24576
#define STG_BYTES 32768
#define SM_TOTAL (3 * STG_BYTES)   // 98304

__global__ __launch_bounds__(256, 2) void gemm_mma(
    const __nv_bfloat16* __restrict__ Ah, const __nv_bfloat16* __restrict__ Al,
    const __nv_bfloat16* __restrict__ Wh, const __nv_bfloat16* __restrict__ Wl,
    float* __restrict__ C)
{
    extern __shared__ char smem[];
    const uint32_t smem_base = smem_u32(smem);

    const int tid  = threadIdx.x;
    const int wid  = tid >> 5;
    const int lane = tid & 31;
    const int wm   = wid & 3;    // M offset wm*32
    const int wn   = wid >> 2;   // N offset wn*64

    const size_t mrow0 = (size_t)blockIdx.y * GBM;
    const size_t nrow0 = (size_t)blockIdx.x * GBN;

    // --- cp.async per-thread addressing ---
    // Each tile: 128 rows x 4 segs = 512 x 16B; 256 threads -> 2 reps/tile.
    const int r0 = tid >> 2;             // 0..63
    const int r1 = r0 + 64;              // 64..127
    const int sg = tid & 3;              // 16B segment
    const uint32_t so0 = (uint32_t)r0 * 64 + (uint32_t)((sg * 16) ^ (((r0 >> 1) & 3) << 4));
    const uint32_t so1 = (uint32_t)r1 * 64 + (uint32_t)((sg * 16) ^ (((r1 >> 1) & 3) << 4));
    const __nv_bfloat16* gAh0 = Ah + (mrow0 + r0) * E_ + sg * 8;
    const __nv_bfloat16* gAh1 = Ah + (mrow0 + r1) * E_ + sg * 8;
    const __nv_bfloat16* gAl0 = Al + (mrow0 + r0) * E_ + sg * 8;
    const __nv_bfloat16* gAl1 = Al + (mrow0 + r1) * E_ + sg * 8;
    const __nv_bfloat16* gWh0 = Wh + (nrow0 + r0) * E_ + sg * 8;
    const __nv_bfloat16* gWh1 = Wh + (nrow0 + r1) * E_ + sg * 8;
    const __nv_bfloat16* gWl0 = Wl + (nrow0 + r0) * E_ + sg * 8;
    const __nv_bfloat16* gWl1 = Wl + (nrow0 + r1) * E_ + sg * 8;

    // --- ldmatrix lane addressing (64B rows) ---
    uint32_t aBase[2], aSwz[2];
#pragma unroll
    for (int mt = 0; mt < 2; mt++) {
        const int r = wm * 32 + mt * 16 + (lane & 15);
        aBase[mt] = (uint32_t)r * 64;
        aSwz[mt]  = (uint32_t)(((r >> 1) & 3) << 4);
    }
    const uint32_t cselA = (uint32_t)(((lane >> 4) & 1) * 16);
    uint32_t bBase[4], bSwz[4];
#pragma unroll
    for (int g = 0; g < 4; g++) {
        const int r = wn * 64 + g * 16 + (lane & 7) + ((lane >> 4) & 1) * 8;
        bBase[g] = (uint32_t)r * 64;
        bSwz[g]  = (uint32_t)(((r >> 1) & 3) << 4);
    }
    const uint32_t cselB = (uint32_t)(((lane >> 3) & 1) * 16);

    float acc[2][8][4];
#pragma unroll
    for (int mt = 0; mt < 2; mt++)
#pragma unroll
        for (int nt = 0; nt < 8; nt++)
#pragma unroll
            for (int r = 0; r < 4; r++) acc[mt][nt][r] = 0.0f;

    auto load_chunk = [&](int ch, int stg) {
        const uint32_t sb = smem_base + (uint32_t)stg * STG_BYTES;
        const int kb = ch * GBK;
        CP_ASYNC16(sb + T_AH + so0, gAh0 + kb);
        CP_ASYNC16(sb + T_AH + so1, gAh1 + kb);
        CP_ASYNC16(sb + T_AL + so0, gAl0 + kb);
        CP_ASYNC16(sb + T_AL + so1, gAl1 + kb);
        CP_ASYNC16(sb + T_WH + so0, gWh0 + kb);
        CP_ASYNC16(sb + T_WH + so1, gWh1 + kb);
        CP_ASYNC16(sb + T_WL + so0, gWl0 + kb);
        CP_ASYNC16(sb + T_WL + so1, gWl1 + kb);
        CP_COMMIT();
    };

    load_chunk(0, 0);
    load_chunk(1, 1);

#pragma unroll 1
    for (int ch = 0; ch < NCHUNK; ch++) {
        if (ch + 1 < NCHUNK) { CP_WAIT(1); } else { CP_WAIT(0); }
        __syncthreads();
        if (ch + 2 < NCHUNK) load_chunk(ch + 2, (ch + 2) % 3);

        const uint32_t sb = smem_base + (uint32_t)(ch % 3) * STG_BYTES;
#pragma unroll
        for (int term = 0; term < 3; term++) {
            const uint32_t baseA = sb + (term == 2 ? T_AL : T_AH);
            const uint32_t baseW = sb + (term == 1 ? T_WL : T_WH);
#pragma unroll
            for (int ks = 0; ks < 2; ks++) {
                const uint32_t kb = (uint32_t)(ks * 32);
                uint32_t a[2][4];
#pragma unroll
                for (int mt = 0; mt < 2; mt++) {
                    const uint32_t ad = baseA + aBase[mt] + ((kb + cselA) ^ aSwz[mt]);
                    asm volatile(
                        "ldmatrix.sync.aligned.m8n8.x4.shared.b16 {%0,%1,%2,%3}, [%4];"
                        : "=r"(a[mt][0]), "=r"(a[mt][1]), "=r"(a[mt][2]), "=r"(a[mt][3])
                        : "r"(ad));
                }
#pragma unroll
                for (int g = 0; g < 4; g++) {
                    uint32_t b0, b1, b2, b3;
                    const uint32_t bd = baseW + bBase[g] + ((kb + cselB) ^ bSwz[g]);
                    asm volatile(
                        "ldmatrix.sync.aligned.m8n8.x4.shared.b16 {%0,%1,%2,%3}, [%4];"
                        : "=r"(b0), "=r"(b1), "=r"(b2), "=r"(b3)
                        : "r"(bd));
#pragma unroll
                    for (int mt = 0; mt < 2; mt++) {
                        asm volatile(
                            "mma.sync.aligned.m16n8k16.row.col.f32.bf16.bf16.f32 "
                            "{%0,%1,%2,%3}, {%4,%5,%6,%7}, {%8,%9}, {%0,%1,%2,%3};"
                            : "+f"(acc[mt][g * 2][0]), "+f"(acc[mt][g * 2][1]),
                              "+f"(acc[mt][g * 2][2]), "+f"(acc[mt][g * 2][3])
                            : "r"(a[mt][0]), "r"(a[mt][1]), "r"(a[mt][2]), "r"(a[mt][3]),
                              "r"(b0), "r"(b1));
                        asm volatile(
                            "mma.sync.aligned.m16n8k16.row.col.f32.bf16.bf16.f32 "
                            "{%0,%1,%2,%3}, {%4,%5,%6,%7}, {%8,%9}, {%0,%1,%2,%3};"
                            : "+f"(acc[mt][g * 2 + 1][0]), "+f"(acc[mt][g * 2 + 1][1]),
                              "+f"(acc[mt][g * 2 + 1][2]), "+f"(acc[mt][g * 2 + 1][3])
                            : "r"(a[mt][0]), "r"(a[mt][1]), "r"(a[mt][2]), "r"(a[mt][3]),
                              "r"(b2), "r"(b3));
                    }
                }
            }
        }
    }

    // Epilogue: warp tile rows wm*32+mt*16+{qr,qr+8}, cols wn*64+nt*8+qc.
    const int qr = lane >> 2;
    const int qc = (lane & 3) * 2;
#pragma unroll
    for (int mt = 0; mt < 2; mt++) {
        const size_t r0e = mrow0 + wm * 32 + mt * 16 + qr;
#pragma unroll
        for (int nt = 0; nt < 8; nt++) {
            const size_t col = nrow0 + wn * 64 + nt * 8 + qc;
            *(float2*)(C + r0e * E_ + col)       = make_float2(acc[mt][nt][0], acc[mt][nt][1]);
            *(float2*)(C + (r0e + 8) * E_ + col) = make_float2(acc[mt][nt][2], acc[mt][nt][3]);
        }
    }
}

// ---------------------------------------------------------------------------
// fp32 -> bf16 hi/lo split conversion (float4 vectorized)
// ---------------------------------------------------------------------------
__global__ __launch_bounds__(256) void conv_split(
    const float* __restrict__ in, __nv_bfloat16* __restrict__ hi,
    __nv_bfloat16* __restrict__ lo, int n4)
{
    int idx = blockIdx.x * 256 + threadIdx.x;
    if (idx >= n4) return;
    float4 v = ((const float4*)in)[idx];
    __nv_bfloat16 h0 = __float2bfloat16(v.x), h1 = __float2bfloat16(v.y);
    __nv_bfloat16 h2 = __float2bfloat16(v.z), h3 = __float2bfloat16(v.w);
    __nv_bfloat16 l0 = __float2bfloat16(v.x - __bfloat162float(h0));
    __nv_bfloat16 l1 = __float2bfloat16(v.y - __bfloat162float(h1));
    __nv_bfloat16 l2 = __float2bfloat16(v.z - __bfloat162float(h2));
    __nv_bfloat16 l3 = __float2bfloat16(v.w - __bfloat162float(h3));
    __nv_bfloat162 hp0; hp0.x = h0; hp0.y = h1;
    __nv_bfloat162 hp1; hp1.x = h2; hp1.y = h3;
    __nv_bfloat162 lp0; lp0.x = l0; lp0.y = l1;
    __nv_bfloat162 lp1; lp1.x = l2; lp1.y = l3;
    uint2 hw, lw;
    hw.x = *(uint32_t*)&hp0; hw.y = *(uint32_t*)&hp1;
    lw.x = *(uint32_t*)&lp0; lw.y = *(uint32_t*)&lp1;
    ((uint2*)hi)[idx] = hw;
    ((uint2*)lo)[idx] = lw;
}

// ---------------------------------------------------------------------------
// Gaussian smoothing along sequence (17 taps, float4 over embed dim),
// reading fp32 V, writing bf16 hi/lo U for GEMM2.
// ---------------------------------------------------------------------------
__global__ __launch_bounds__(256) void smooth_kernel(
    const float* __restrict__ V, __nv_bfloat16* __restrict__ Uh,
    __nv_bfloat16* __restrict__ Ul)
{
    const float wt[RAD + 1] = {1.0f, 0.60653066f, 0.13533528f, 0.011108997f,
                               3.3546263e-4f, 3.7266532e-6f, 1.5229979e-8f,
                               2.2897348e-11f, 1.2664166e-14f};
    const int n = blockIdx.x;        // b*L + q
    const int b = n >> 11;
    const int q = n & (L_ - 1);
    const int e = threadIdx.x * 4;   // 4 consecutive embed cols
    const int h = e >> 7;            // head

    int c;
    switch (h) {
        case 0: case 5: c = q;      break;   // center
        case 1: case 6: c = q - 1;  break;   // left
        case 2: case 7: c = q + 1;  break;   // right
        case 3:         c = 0;      break;   // first
        default:        c = L_ - 1; break;   // last
    }

    float ax = 0.f, ay = 0.f, az = 0.f, aw = 0.f, wsum = 0.f;
#pragma unroll
    for (int d = -RAD; d <= RAD; d++) {
        const int j = c + d;
        if (j >= 0 && j < L_) {
            const float w = wt[d < 0 ? -d : d];
            wsum += w;
            const float4 v = *(const float4*)(V + ((size_t)b * L_ + j) * E_ + e);
            ax = fmaf(w, v.x, ax); ay = fmaf(w, v.y, ay);
            az = fmaf(w, v.z, az); aw = fmaf(w, v.w, aw);
        }
    }
    const float inv = 1.0f / wsum;
    ax *= inv; ay *= inv; az *= inv; aw *= inv;

    __nv_bfloat16 h0 = __float2bfloat16(ax), h1 = __float2bfloat16(ay);
    __nv_bfloat16 h2 = __float2bfloat16(az), h3 = __float2bfloat16(aw);
    __nv_bfloat16 l0 = __float2bfloat16(ax - __bfloat162float(h0));
    __nv_bfloat16 l1 = __float2bfloat16(ay - __bfloat162float(h1));
    __nv_bfloat16 l2 = __float2bfloat16(az - __bfloat162float(h2));
    __nv_bfloat16 l3 = __float2bfloat16(aw - __bfloat162float(h3));
    __nv_bfloat162 hp0; hp0.x = h0; hp0.y = h1;
    __nv_bfloat162 hp1; hp1.x = h2; hp1.y = h3;
    __nv_bfloat162 lp0; lp0.x = l0; lp0.y = l1;
    __nv_bfloat162 lp1; lp1.x = l2; lp1.y = l3;
    uint2 hw, lw;
    hw.x = *(uint32_t*)&hp0; hw.y = *(uint32_t*)&hp1;
    lw.x = *(uint32_t*)&lp0; lw.y = *(uint32_t*)&lp1;
    const size_t o = ((size_t)n * E_ + e) >> 2;
    ((uint2*)Uh)[o] = hw;
    ((uint2*)Ul)[o] = lw;
}

// ---------------------------------------------------------------------------
extern "C" void kernel_launch(void* const* d_in, const int* in_sizes, int n_in,
                              void* d_out, int out_size)
{
    (void)in_sizes; (void)n_in; (void)out_size;
    const float* x     = (const float*)d_in[0];
    const float* W_in  = (const float*)d_in[1];
    const float* W_out = (const float*)d_in[2];
    float* out = (float*)d_out;

    __nv_bfloat16 *Xh, *Xl, *Wih, *Wil, *Woh, *Wol, *Uh, *Ul;
    float* Vf;
    cudaGetSymbolAddress((void**)&Xh, g_Xh);
    cudaGetSymbolAddress((void**)&Xl, g_Xl);
    cudaGetSymbolAddress((void**)&Wih, g_Wih);
    cudaGetSymbolAddress((void**)&Wil, g_Wil);
    cudaGetSymbolAddress((void**)&Woh, g_Woh);
    cudaGetSymbolAddress((void**)&Wol, g_Wol);
    cudaGetSymbolAddress((void**)&Vf, g_Vf);
    cudaGetSymbolAddress((void**)&Uh, g_Uh);
    cudaGetSymbolAddress((void**)&Ul, g_Ul);

    cudaFuncSetAttribute(gemm_mma, cudaFuncAttributeMaxDynamicSharedMemorySize, SM_TOTAL);

    // Split conversions
    conv_split<<<(M_ * E_ / 4 + 255) / 256, 256>>>(x, Xh, Xl, M_ * E_ / 4);
    conv_split<<<(E_ * E_ / 4 + 255) / 256, 256>>>(W_in, Wih, Wil, E_ * E_ / 4);
    conv_split<<<(E_ * E_ / 4 + 255) / 256, 256>>>(W_out, Woh, Wol, E_ * E_ / 4);

    dim3 gridGemm(E_ / GBN, M_ / GBM);   // (8, 128)
    // V = X @ W_in^T   (fp32 out for smoothing)
    gemm_mma<<<gridGemm, 256, SM_TOTAL>>>(Xh, Xl, Wih, Wil, Vf);
    // U = gaussian smooth of V (bf16 hi/lo out)
    smooth_kernel<<<M_, 256>>>(Vf, Uh, Ul);
    // out = U @ W_out^T (fp32 out)
    gemm_mma<<<gridGemm, 256, SM_TOTAL>>>(Uh, Ul, Woh, Wol, out);
}

// round 9
// speedup vs baseline: 1.3597x; 1.0866x over previous
#include <cuda_runtime.h>
#include <cuda_bf16.h>
#include <cstdint>

// Problem dims (fixed)
#define B_   8
#define L_   2048
#define E_   1024
#define M_   (B_ * L_)   // 16384
#define RAD  8

// ---------------------------------------------------------------------------
// Scratch (__device__ globals; allocation-free rule)
// ---------------------------------------------------------------------------
__device__ __nv_bfloat16 g_Xh[(size_t)M_ * E_];
__device__ __nv_bfloat16 g_Xl[(size_t)M_ * E_];
__device__ __nv_bfloat16 g_Wih[(size_t)E_ * E_];
__device__ __nv_bfloat16 g_Wil[(size_t)E_ * E_];
__device__ __nv_bfloat16 g_Woh[(size_t)E_ * E_];
__device__ __nv_bfloat16 g_Wol[(size_t)E_ * E_];
__device__ float         g_Vf [(size_t)M_ * E_];
__device__ __nv_bfloat16 g_Uh[(size_t)M_ * E_];
__device__ __nv_bfloat16 g_Ul[(size_t)M_ * E_];

__device__ __forceinline__ uint32_t smem_u32(const void* p) {
    uint32_t a;
    asm("{ .reg .u64 t; cvta.to.shared.u64 t, %1; cvt.u32.u64 %0, t; }" : "=r"(a) : "l"(p));
    return a;
}

#define CP_ASYNC16(dst, src) \
    asm volatile("cp.async.cg.shared.global [%0], [%1], 16;" :: "r"(dst), "l"(src))
#define CP_COMMIT() asm volatile("cp.async.commit_group;")
#define CP_WAIT(n)  asm volatile("cp.async.wait_group %0;" :: "n"(n))

#define LDSM_X4(r0, r1, r2, r3, addr)                                        \
    asm volatile("ldmatrix.sync.aligned.m8n8.x4.shared.b16 {%0,%1,%2,%3}, [%4];" \
                 : "=r"(r0), "=r"(r1), "=r"(r2), "=r"(r3) : "r"(addr))

#define MMA16816(acc, ar, b0, b1)                                            \
    asm volatile("mma.sync.aligned.m16n8k16.row.col.f32.bf16.bf16.f32 "      \
                 "{%0,%1,%2,%3}, {%4,%5,%6,%7}, {%8,%9}, {%0,%1,%2,%3};"     \
                 : "+f"((acc)[0]), "+f"((acc)[1]), "+f"((acc)[2]), "+f"((acc)[3]) \
                 : "r"((ar)[0]), "r"((ar)[1]), "r"((ar)[2]), "r"((ar)[3]),   \
                   "r"(b0), "r"(b1))

// ---------------------------------------------------------------------------
// GEMM: C[M,1024] = A[M,1024] @ W[1024,1024]^T via bf16 split (3 HMMA terms,
// all accumulating into the same fp32 acc). BM=BN=128, BK=32, 256 threads,
// warp tile 32x64, 3-stage cp.async, 2 CTAs/SM.
// Fragments Ah/Al/Bh/Bl loaded ONCE per k-step and reused by all 3 terms:
// 12 ldmatrix.x4 per k-step instead of 18 (-33% smem fragment traffic).
// ---------------------------------------------------------------------------
#define GBM 128
#define GBN 128
#define GBK 32
#define NCHUNK (E_ / GBK)   // 32

#define T_AH 0
#define T_AL 8192
#define T_WH 16384
#define T_WL 24576
#define STG_BYTES 32768
#define SM_TOTAL (3 * STG_BYTES)   // 98304

__global__ __launch_bounds__(256, 2) void gemm_mma(
    const __nv_bfloat16* __restrict__ Ah, const __nv_bfloat16* __restrict__ Al,
    const __nv_bfloat16* __restrict__ Wh, const __nv_bfloat16* __restrict__ Wl,
    float* __restrict__ C)
{
    extern __shared__ char smem[];
    const uint32_t smem_base = smem_u32(smem);

    const int tid  = threadIdx.x;
    const int wid  = tid >> 5;
    const int lane = tid & 31;
    const int wm   = wid & 3;    // M offset wm*32
    const int wn   = wid >> 2;   // N offset wn*64

    const size_t mrow0 = (size_t)blockIdx.y * GBM;
    const size_t nrow0 = (size_t)blockIdx.x * GBN;

    // --- cp.async per-thread addressing (each tile: 128 rows x 4 x 16B) ---
    const int r0 = tid >> 2;
    const int r1 = r0 + 64;
    const int sg = tid & 3;
    const uint32_t so0 = (uint32_t)r0 * 64 + (uint32_t)((sg * 16) ^ (((r0 >> 1) & 3) << 4));
    const uint32_t so1 = (uint32_t)r1 * 64 + (uint32_t)((sg * 16) ^ (((r1 >> 1) & 3) << 4));
    const __nv_bfloat16* gAh0 = Ah + (mrow0 + r0) * E_ + sg * 8;
    const __nv_bfloat16* gAh1 = Ah + (mrow0 + r1) * E_ + sg * 8;
    const __nv_bfloat16* gAl0 = Al + (mrow0 + r0) * E_ + sg * 8;
    const __nv_bfloat16* gAl1 = Al + (mrow0 + r1) * E_ + sg * 8;
    const __nv_bfloat16* gWh0 = Wh + (nrow0 + r0) * E_ + sg * 8;
    const __nv_bfloat16* gWh1 = Wh + (nrow0 + r1) * E_ + sg * 8;
    const __nv_bfloat16* gWl0 = Wl + (nrow0 + r0) * E_ + sg * 8;
    const __nv_bfloat16* gWl1 = Wl + (nrow0 + r1) * E_ + sg * 8;

    // --- ldmatrix lane addressing (64B rows) ---
    uint32_t aBase[2], aSwz[2];
#pragma unroll
    for (int mt = 0; mt < 2; mt++) {
        const int r = wm * 32 + mt * 16 + (lane & 15);
        aBase[mt] = (uint32_t)r * 64;
        aSwz[mt]  = (uint32_t)(((r >> 1) & 3) << 4);
    }
    const uint32_t cselA = (uint32_t)(((lane >> 4) & 1) * 16);
    uint32_t bBase[4], bSwz[4];
#pragma unroll
    for (int g = 0; g < 4; g++) {
        const int r = wn * 64 + g * 16 + (lane & 7) + ((lane >> 4) & 1) * 8;
        bBase[g] = (uint32_t)r * 64;
        bSwz[g]  = (uint32_t)(((r >> 1) & 3) << 4);
    }
    const uint32_t cselB = (uint32_t)(((lane >> 3) & 1) * 16);

    float acc[2][8][4];
#pragma unroll
    for (int mt = 0; mt < 2; mt++)
#pragma unroll
        for (int nt = 0; nt < 8; nt++)
#pragma unroll
            for (int r = 0; r < 4; r++) acc[mt][nt][r] = 0.0f;

    auto load_chunk = [&](int ch, int stg) {
        const uint32_t sb = smem_base + (uint32_t)stg * STG_BYTES;
        const int kb = ch * GBK;
        CP_ASYNC16(sb + T_AH + so0, gAh0 + kb);
        CP_ASYNC16(sb + T_AH + so1, gAh1 + kb);
        CP_ASYNC16(sb + T_AL + so0, gAl0 + kb);
        CP_ASYNC16(sb + T_AL + so1, gAl1 + kb);
        CP_ASYNC16(sb + T_WH + so0, gWh0 + kb);
        CP_ASYNC16(sb + T_WH + so1, gWh1 + kb);
        CP_ASYNC16(sb + T_WL + so0, gWl0 + kb);
        CP_ASYNC16(sb + T_WL + so1, gWl1 + kb);
        CP_COMMIT();
    };

    load_chunk(0, 0);
    load_chunk(1, 1);

#pragma unroll 1
    for (int ch = 0; ch < NCHUNK; ch++) {
        if (ch + 1 < NCHUNK) { CP_WAIT(1); } else { CP_WAIT(0); }
        __syncthreads();
        if (ch + 2 < NCHUNK) load_chunk(ch + 2, (ch + 2) % 3);

        const uint32_t sb = smem_base + (uint32_t)(ch % 3) * STG_BYTES;
#pragma unroll
        for (int ks = 0; ks < 2; ks++) {
            const uint32_t kb = (uint32_t)(ks * 32);
            // A fragments (hi+lo), loaded once per k-step
            uint32_t ah[2][4], al[2][4];
#pragma unroll
            for (int mt = 0; mt < 2; mt++) {
                const uint32_t off = aBase[mt] + ((kb + cselA) ^ aSwz[mt]);
                LDSM_X4(ah[mt][0], ah[mt][1], ah[mt][2], ah[mt][3], sb + T_AH + off);
                LDSM_X4(al[mt][0], al[mt][1], al[mt][2], al[mt][3], sb + T_AL + off);
            }
#pragma unroll
            for (int g = 0; g < 4; g++) {
                const uint32_t boff = bBase[g] + ((kb + cselB) ^ bSwz[g]);
                uint32_t bh0, bh1, bh2, bh3, bl0, bl1, bl2, bl3;
                LDSM_X4(bh0, bh1, bh2, bh3, sb + T_WH + boff);
                LDSM_X4(bl0, bl1, bl2, bl3, sb + T_WL + boff);
#pragma unroll
                for (int mt = 0; mt < 2; mt++) {
                    // term AhBh
                    MMA16816(acc[mt][g * 2],     ah[mt], bh0, bh1);
                    MMA16816(acc[mt][g * 2 + 1], ah[mt], bh2, bh3);
                    // term AhBl
                    MMA16816(acc[mt][g * 2],     ah[mt], bl0, bl1);
                    MMA16816(acc[mt][g * 2 + 1], ah[mt], bl2, bl3);
                    // term AlBh
                    MMA16816(acc[mt][g * 2],     al[mt], bh0, bh1);
                    MMA16816(acc[mt][g * 2 + 1], al[mt], bh2, bh3);
                }
            }
        }
    }

    // Epilogue
    const int qr = lane >> 2;
    const int qc = (lane & 3) * 2;
#pragma unroll
    for (int mt = 0; mt < 2; mt++) {
        const size_t r0e = mrow0 + wm * 32 + mt * 16 + qr;
#pragma unroll
        for (int nt = 0; nt < 8; nt++) {
            const size_t col = nrow0 + wn * 64 + nt * 8 + qc;
            *(float2*)(C + r0e * E_ + col)       = make_float2(acc[mt][nt][0], acc[mt][nt][1]);
            *(float2*)(C + (r0e + 8) * E_ + col) = make_float2(acc[mt][nt][2], acc[mt][nt][3]);
        }
    }
}

// ---------------------------------------------------------------------------
// fp32 -> bf16 hi/lo split conversion (float4 vectorized)
// ---------------------------------------------------------------------------
__global__ __launch_bounds__(256) void conv_split(
    const float* __restrict__ in, __nv_bfloat16* __restrict__ hi,
    __nv_bfloat16* __restrict__ lo, int n4)
{
    int idx = blockIdx.x * 256 + threadIdx.x;
    if (idx >= n4) return;
    float4 v = ((const float4*)in)[idx];
    __nv_bfloat16 h0 = __float2bfloat16(v.x), h1 = __float2bfloat16(v.y);
    __nv_bfloat16 h2 = __float2bfloat16(v.z), h3 = __float2bfloat16(v.w);
    __nv_bfloat16 l0 = __float2bfloat16(v.x - __bfloat162float(h0));
    __nv_bfloat16 l1 = __float2bfloat16(v.y - __bfloat162float(h1));
    __nv_bfloat16 l2 = __float2bfloat16(v.z - __bfloat162float(h2));
    __nv_bfloat16 l3 = __float2bfloat16(v.w - __bfloat162float(h3));
    __nv_bfloat162 hp0; hp0.x = h0; hp0.y = h1;
    __nv_bfloat162 hp1; hp1.x = h2; hp1.y = h3;
    __nv_bfloat162 lp0; lp0.x = l0; lp0.y = l1;
    __nv_bfloat162 lp1; lp1.x = l2; lp1.y = l3;
    uint2 hw, lw;
    hw.x = *(uint32_t*)&hp0; hw.y = *(uint32_t*)&hp1;
    lw.x = *(uint32_t*)&lp0; lw.y = *(uint32_t*)&lp1;
    ((uint2*)hi)[idx] = hw;
    ((uint2*)lo)[idx] = lw;
}

// ---------------------------------------------------------------------------
// Gaussian smoothing along sequence (17 taps, float4 over embed dim),
// reading fp32 V, writing bf16 hi/lo U for GEMM2.
// ---------------------------------------------------------------------------
__global__ __launch_bounds__(256) void smooth_kernel(
    const float* __restrict__ V, __nv_bfloat16* __restrict__ Uh,
    __nv_bfloat16* __restrict__ Ul)
{
    const float wt[RAD + 1] = {1.0f, 0.60653066f, 0.13533528f, 0.011108997f,
                               3.3546263e-4f, 3.7266532e-6f, 1.5229979e-8f,
                               2.2897348e-11f, 1.2664166e-14f};
    const int n = blockIdx.x;        // b*L + q
    const int b = n >> 11;
    const int q = n & (L_ - 1);
    const int e = threadIdx.x * 4;   // 4 consecutive embed cols
    const int h = e >> 7;            // head

    int c;
    switch (h) {
        case 0: case 5: c = q;      break;   // center
        case 1: case 6: c = q - 1;  break;   // left
        case 2: case 7: c = q + 1;  break;   // right
        case 3:         c = 0;      break;   // first
        default:        c = L_ - 1; break;   // last
    }

    float ax = 0.f, ay = 0.f, az = 0.f, aw = 0.f, wsum = 0.f;
#pragma unroll
    for (int d = -RAD; d <= RAD; d++) {
        const int j = c + d;
        if (j >= 0 && j < L_) {
            const float w = wt[d < 0 ? -d : d];
            wsum += w;
            const float4 v = *(const float4*)(V + ((size_t)b * L_ + j) * E_ + e);
            ax = fmaf(w, v.x, ax); ay = fmaf(w, v.y, ay);
            az = fmaf(w, v.z, az); aw = fmaf(w, v.w, aw);
        }
    }
    const float inv = 1.0f / wsum;
    ax *= inv; ay *= inv; az *= inv; aw *= inv;

    __nv_bfloat16 h0 = __float2bfloat16(ax), h1 = __float2bfloat16(ay);
    __nv_bfloat16 h2 = __float2bfloat16(az), h3 = __float2bfloat16(aw);
    __nv_bfloat16 l0 = __float2bfloat16(ax - __bfloat162float(h0));
    __nv_bfloat16 l1 = __float2bfloat16(ay - __bfloat162float(h1));
    __nv_bfloat16 l2 = __float2bfloat16(az - __bfloat162float(h2));
    __nv_bfloat16 l3 = __float2bfloat16(aw - __bfloat162float(h3));
    __nv_bfloat162 hp0; hp0.x = h0; hp0.y = h1;
    __nv_bfloat162 hp1; hp1.x = h2; hp1.y = h3;
    __nv_bfloat162 lp0; lp0.x = l0; lp0.y = l1;
    __nv_bfloat162 lp1; lp1.x = l2; lp1.y = l3;
    uint2 hw, lw;
    hw.x = *(uint32_t*)&hp0; hw.y = *(uint32_t*)&hp1;
    lw.x = *(uint32_t*)&lp0; lw.y = *(uint32_t*)&lp1;
    const size_t o = ((size_t)n * E_ + e) >> 2;
    ((uint2*)Uh)[o] = hw;
    ((uint2*)Ul)[o] = lw;
}

// ---------------------------------------------------------------------------
extern "C" void kernel_launch(void* const* d_in, const int* in_sizes, int n_in,
                              void* d_out, int out_size)
{
    (void)in_sizes; (void)n_in; (void)out_size;
    const float* x     = (const float*)d_in[0];
    const float* W_in  = (const float*)d_in[1];
    const float* W_out = (const float*)d_in[2];
    float* out = (float*)d_out;

    __nv_bfloat16 *Xh, *Xl, *Wih, *Wil, *Woh, *Wol, *Uh, *Ul;
    float* Vf;
    cudaGetSymbolAddress((void**)&Xh, g_Xh);
    cudaGetSymbolAddress((void**)&Xl, g_Xl);
    cudaGetSymbolAddress((void**)&Wih, g_Wih);
    cudaGetSymbolAddress((void**)&Wil, g_Wil);
    cudaGetSymbolAddress((void**)&Woh, g_Woh);
    cudaGetSymbolAddress((void**)&Wol, g_Wol);
    cudaGetSymbolAddress((void**)&Vf, g_Vf);
    cudaGetSymbolAddress((void**)&Uh, g_Uh);
    cudaGetSymbolAddress((void**)&Ul, g_Ul);

    cudaFuncSetAttribute(gemm_mma, cudaFuncAttributeMaxDynamicSharedMemorySize, SM_TOTAL);

    // Split conversions
    conv_split<<<(M_ * E_ / 4 + 255) / 256, 256>>>(x, Xh, Xl, M_ * E_ / 4);
    conv_split<<<(E_ * E_ / 4 + 255) / 256, 256>>>(W_in, Wih, Wil, E_ * E_ / 4);
    conv_split<<<(E_ * E_ / 4 + 255) / 256, 256>>>(W_out, Woh, Wol, E_ * E_ / 4);

    dim3 gridGemm(E_ / GBN, M_ / GBM);   // (8, 128)
    // V = X @ W_in^T   (fp32 out for smoothing)
    gemm_mma<<<gridGemm, 256, SM_TOTAL>>>(Xh, Xl, Wih, Wil, Vf);
    // U = gaussian smooth of V (bf16 hi/lo out)
    smooth_kernel<<<M_, 256>>>(Vf, Uh, Ul);
    // out = U @ W_out^T (fp32 out)
    gemm_mma<<<gridGemm, 256, SM_TOTAL>>>(Uh, Ul, Woh, Wol, out);
}